// round 8
// baseline (speedup 1.0000x reference)
#include <cuda_runtime.h>
#include <cuda_bf16.h>
#include <math.h>
#include <stdint.h>

#define B_ 256
#define S_ 120
#define T_ 24
#define D_ 216
#define H_ 1024
#define G_ 4096           // 4*H
#define KP 1280           // padded K (1024 h + 216 x + 40 zero)
#define XP 256            // padded x row width
#define BK 32
#define NCH (KP / BK)     // 40
// per-stage: A hi/lo + B hi/lo, each 64 rows x 80B, +64B inter-split shift to
// kill the 2-way cp.async store bank conflict (split regions 64B-rotated).
#define A_PITCH 80
#define SPLIT_BYTES 5184               // 64*80 + 64 shift
#define STAGE_BYTES (4 * SPLIT_BYTES)  // 20736
#define NSTAGE 3
#define SMEM_DYN (NSTAGE * STAGE_BYTES)  // 62208

// ---------------- device globals (no allocations allowed) --------------------
__device__ __align__(16) __nv_bfloat16 g_Wp_hi[G_ * KP];      // permuted, split
__device__ __align__(16) __nv_bfloat16 g_Wp_lo[G_ * KP];
__device__ __align__(16) __nv_bfloat16 g_xe_hi[S_ * B_ * XP]; // encoder x splits
__device__ __align__(16) __nv_bfloat16 g_xe_lo[S_ * B_ * XP];
__device__ __align__(16) __nv_bfloat16 g_xd_hi[B_ * XP];      // decoder x splits
__device__ __align__(16) __nv_bfloat16 g_xd_lo[B_ * XP];
__device__ __align__(16) __nv_bfloat16 g_ah_hi[2][B_ * H_];   // h splits, ping-pong
__device__ __align__(16) __nv_bfloat16 g_ah_lo[2][B_ * H_];
__device__ float g_hf[B_ * H_];       // fp32 h (projection input)
__device__ float g_c[B_ * H_];        // cell state
__device__ float g_bp[G_];            // permuted combined bias
__device__ float g_proj[8][B_ * D_];  // split-K projection partials

__device__ __forceinline__ float sigf(float v) { return 1.f / (1.f + expf(-v)); }

// ---------------- PTX helpers (baseline sm_80+ only) -------------------------
__device__ __forceinline__ uint32_t smem_u32(const void* p) {
    uint32_t a;
    asm("{ .reg .u64 t; cvta.to.shared.u64 t, %1; cvt.u32.u64 %0, t; }"
        : "=r"(a) : "l"(p));
    return a;
}
#define CP_ASYNC16(dst, src) \
    asm volatile("cp.async.ca.shared.global [%0], [%1], 16;" :: "r"(dst), "l"(src))
#define CP_COMMIT() asm volatile("cp.async.commit_group;" ::: "memory")
#define CP_WAIT1()  asm volatile("cp.async.wait_group 1;" ::: "memory")
#define CP_WAIT0()  asm volatile("cp.async.wait_group 0;" ::: "memory")

#define LDSM_X4(r0, r1, r2, r3, a) \
    asm volatile("ldmatrix.sync.aligned.m8n8.x4.shared.b16 {%0,%1,%2,%3}, [%4];" \
                 : "=r"(r0), "=r"(r1), "=r"(r2), "=r"(r3) : "r"(a))

#define MMA16816(d, a, b) \
    asm volatile("mma.sync.aligned.m16n8k16.row.col.f32.bf16.bf16.f32 " \
                 "{%0,%1,%2,%3},{%4,%5,%6,%7},{%8,%9},{%0,%1,%2,%3};" \
                 : "+f"((d)[0]), "+f"((d)[1]), "+f"((d)[2]), "+f"((d)[3]) \
                 : "r"((a)[0]), "r"((a)[1]), "r"((a)[2]), "r"((a)[3]), \
                   "r"((b)[0]), "r"((b)[1]))

// ---------------- prep kernels ----------------------------------------------
// Permutation: permuted col p -> bn=p>>6, c=p&63, u=c>>2, q=c&3, unit j=bn*16+u,
// original weight row = q*H_ + j. A CTA's 64 cols = 16 units x 4 gates.
__global__ void prep_weights(const float* __restrict__ W_ih,
                             const float* __restrict__ W_hh,
                             const float* __restrict__ b_ih,
                             const float* __restrict__ b_hh)
{
    int idx = blockIdx.x * blockDim.x + threadIdx.x;  // G_*KP threads
    int p = idx / KP, k = idx - p * KP;
    int bn = p >> 6, c = p & 63, u = c >> 2, q = c & 3;
    int j = bn * 16 + u;
    int orig = q * H_ + j;
    float w = 0.f;
    if (k < H_) w = W_hh[orig * H_ + k];
    else if (k < H_ + D_) w = W_ih[orig * D_ + (k - H_)];
    __nv_bfloat16 hi = __float2bfloat16(w);
    g_Wp_hi[idx] = hi;
    g_Wp_lo[idx] = __float2bfloat16(w - __bfloat162float(hi));
    if (k == 0) g_bp[p] = b_ih[orig] + b_hh[orig];
}

__global__ void prep_xe(const float* __restrict__ src)
{
    int idx = blockIdx.x * blockDim.x + threadIdx.x;  // S_*B_*XP threads
    int t = idx >> 16;            // B_*XP = 65536
    int r = idx & 65535;
    int b = r >> 8, kk = r & 255;
    float v = (kk < D_) ? src[(b * S_ + t) * D_ + kk] : 0.f;
    __nv_bfloat16 hi = __float2bfloat16(v);
    g_xe_hi[idx] = hi;
    g_xe_lo[idx] = __float2bfloat16(v - __bfloat162float(hi));
}

__global__ void init_state()
{
    int idx = blockIdx.x * blockDim.x + threadIdx.x;
    if (idx < B_ * H_) {
        g_c[idx] = 0.f;
        g_ah_hi[0][idx] = __float2bfloat16(0.f);
        g_ah_lo[0][idx] = __float2bfloat16(0.f);
    }
    if (idx < B_ * XP) {
        g_xd_hi[idx] = __float2bfloat16(0.f);
        g_xd_lo[idx] = __float2bfloat16(0.f);
    }
}

// ---------------- fused LSTM step: HMMA split-bf16 GEMM + cell ---------------
// grid (64, 4): blockIdx.x = N tile (64 permuted cols = 16 units),
//               blockIdx.y = M tile (64 batch rows).
// 128 threads = 4 warps in 2x2 layout, warp tile 32x32 (halves smem-crossbar
// bytes per MAC vs 16x32). 3-stage cp.async pipeline, 1 sync per chunk.
__global__ void __launch_bounds__(128, 3)
lstm_step_mma(int hbuf, int xsel, int xoff)
{
    extern __shared__ __align__(128) char smem[];
    const uint32_t sb = smem_u32(smem);
    const int tid = threadIdx.x;
    const int wid = tid >> 5;
    const int lane = tid & 31;
    const int bn = blockIdx.x;
    const int m0 = blockIdx.y << 6;
    const int n0 = bn << 6;

    const __nv_bfloat16* __restrict__ ah_hi = g_ah_hi[hbuf];
    const __nv_bfloat16* __restrict__ ah_lo = g_ah_lo[hbuf];
    const __nv_bfloat16* __restrict__ x_hi = xsel ? g_xd_hi : (g_xe_hi + xoff);
    const __nv_bfloat16* __restrict__ x_lo = xsel ? g_xd_lo : (g_xe_lo + xoff);
    const __nv_bfloat16* __restrict__ wp_hi = g_Wp_hi;
    const __nv_bfloat16* __restrict__ wp_lo = g_Wp_lo;

    // stage layout: [A_hi | A_lo | B_hi | B_lo], each SPLIT_BYTES (64B-rotated
    // so an 8-thread store phase covers all 32 banks).
    // loader: A 512 x 16B + B 512 x 16B per stage -> 8 cp.async per thread.
    auto load_stage = [&](int ch, int slot) {
        uint32_t s = sb + slot * STAGE_BYTES;
        #pragma unroll
        for (int i = 0; i < 4; i++) {
            int idx = i * 128 + tid;
            int row = idx >> 3, rem = idx & 7;
            int split = rem >> 2, c4 = rem & 3;
            const __nv_bfloat16* g;
            if (ch < 32)
                g = (split ? ah_lo : ah_hi) + (size_t)(m0 + row) * H_ + ch * BK + c4 * 8;
            else
                g = (split ? x_lo : x_hi) + (size_t)(m0 + row) * XP + (ch - 32) * BK + c4 * 8;
            CP_ASYNC16(s + split * SPLIT_BYTES + row * A_PITCH + c4 * 16, g);
        }
        #pragma unroll
        for (int i = 0; i < 4; i++) {
            int idx = i * 128 + tid;
            int row = idx >> 3, rem = idx & 7;
            int split = rem >> 2, c4 = rem & 3;
            const __nv_bfloat16* g =
                (split ? wp_lo : wp_hi) + (size_t)(n0 + row) * KP + ch * BK + c4 * 8;
            CP_ASYNC16(s + (2 + split) * SPLIT_BYTES + row * A_PITCH + c4 * 16, g);
        }
    };

    const int warpM = wid & 1;    // rows warpM*32
    const int warpN = wid >> 1;   // cols warpN*32

    // split accumulators: accA gets hi*hi (1-deep chain), accB both cross terms.
    float accA[2][4][4], accB[2][4][4];
    #pragma unroll
    for (int mt = 0; mt < 2; mt++)
        #pragma unroll
        for (int j = 0; j < 4; j++)
            #pragma unroll
            for (int q = 0; q < 4; q++) { accA[mt][j][q] = 0.f; accB[mt][j][q] = 0.f; }

    // ldmatrix lane-address components (constant per thread)
    const int tsel = lane >> 3;          // tile index 0..3
    const int aRow = (tsel & 1) * 8 + (lane & 7);
    const int aKof = (tsel >> 1) * 16;   // bytes
    const int bRow = (tsel >> 1) * 8 + (lane & 7);
    const int bKof = (tsel & 1) * 16;    // bytes

    load_stage(0, 0); CP_COMMIT();
    load_stage(1, 1); CP_COMMIT();

    #pragma unroll 1
    for (int ch = 0; ch < NCH; ch++) {
        CP_WAIT1();                 // stage ch resident
        __syncthreads();
        if (ch + 2 < NCH) load_stage(ch + 2, (ch + 2) % NSTAGE);
        CP_COMMIT();

        uint32_t s = sb + (ch % NSTAGE) * STAGE_BYTES;
        #pragma unroll
        for (int kh = 0; kh < 2; kh++) {
            uint32_t a_hi[2][4], a_lo[2][4];
            #pragma unroll
            for (int mt = 0; mt < 2; mt++) {
                uint32_t ra = s + (warpM * 32 + mt * 16 + aRow) * A_PITCH
                                + kh * 32 + aKof;
                LDSM_X4(a_hi[mt][0], a_hi[mt][1], a_hi[mt][2], a_hi[mt][3], ra);
                LDSM_X4(a_lo[mt][0], a_lo[mt][1], a_lo[mt][2], a_lo[mt][3],
                        ra + SPLIT_BYTES);
            }
            uint32_t b_hi[4][2], b_lo[4][2];
            #pragma unroll
            for (int gq = 0; gq < 2; gq++) {
                uint32_t rb = s + 2 * SPLIT_BYTES
                                + (warpN * 32 + gq * 16 + bRow) * A_PITCH
                                + kh * 32 + bKof;
                uint32_t r0, r1, r2, r3;
                LDSM_X4(r0, r1, r2, r3, rb);
                b_hi[gq * 2 + 0][0] = r0; b_hi[gq * 2 + 0][1] = r1;
                b_hi[gq * 2 + 1][0] = r2; b_hi[gq * 2 + 1][1] = r3;
                LDSM_X4(r0, r1, r2, r3, rb + SPLIT_BYTES);
                b_lo[gq * 2 + 0][0] = r0; b_lo[gq * 2 + 0][1] = r1;
                b_lo[gq * 2 + 1][0] = r2; b_lo[gq * 2 + 1][1] = r3;
            }
            #pragma unroll
            for (int mt = 0; mt < 2; mt++)
                #pragma unroll
                for (int ni = 0; ni < 4; ni++) {
                    MMA16816(accA[mt][ni], a_hi[mt], b_hi[ni]);
                    MMA16816(accB[mt][ni], a_hi[mt], b_lo[ni]);
                    MMA16816(accB[mt][ni], a_lo[mt], b_hi[ni]);
                }
        }
    }
    CP_WAIT0();
    __syncthreads();

    // ---- epilogue: stage gates through smem, fused LSTM cell ----
    float* gbuf = (float*)smem;           // [64][68] f32 = 17.4KB (reuses stages)
    const int GP = 68;
    #pragma unroll
    for (int mt = 0; mt < 2; mt++)
        #pragma unroll
        for (int ni = 0; ni < 4; ni++) {
            int r0 = warpM * 32 + mt * 16 + (lane >> 2);
            int c0 = warpN * 32 + ni * 8 + 2 * (lane & 3);
            gbuf[r0 * GP + c0]           = accA[mt][ni][0] + accB[mt][ni][0];
            gbuf[r0 * GP + c0 + 1]       = accA[mt][ni][1] + accB[mt][ni][1];
            gbuf[(r0 + 8) * GP + c0]     = accA[mt][ni][2] + accB[mt][ni][2];
            gbuf[(r0 + 8) * GP + c0 + 1] = accA[mt][ni][3] + accB[mt][ni][3];
        }
    __syncthreads();

    {
        const int u = tid & 15;           // local unit 0..15
        const int rg = tid >> 4;          // row group 0..7 (8 rows each)
        const int j = bn * 16 + u;        // global hidden unit
        const float bi = g_bp[n0 + u * 4 + 0];
        const float bf = g_bp[n0 + u * 4 + 1];
        const float bg = g_bp[n0 + u * 4 + 2];
        const float bo = g_bp[n0 + u * 4 + 3];
        __nv_bfloat16* __restrict__ oh = g_ah_hi[1 - hbuf];
        __nv_bfloat16* __restrict__ ol = g_ah_lo[1 - hbuf];
        #pragma unroll
        for (int rr = 0; rr < 8; rr++) {
            int r = rg * 8 + rr;
            const float* gr = &gbuf[r * GP + u * 4];
            float gi = gr[0] + bi;
            float gf = gr[1] + bf;
            float gg = gr[2] + bg;
            float go = gr[3] + bo;
            size_t idx = (size_t)(m0 + r) * H_ + j;
            float cn = sigf(gf) * g_c[idx] + sigf(gi) * tanhf(gg);
            g_c[idx] = cn;
            float hn = sigf(go) * tanhf(cn);
            g_hf[idx] = hn;
            __nv_bfloat16 hh = __float2bfloat16(hn);
            oh[idx] = hh;
            ol[idx] = __float2bfloat16(hn - __bfloat162float(hh));
        }
    }
}

// ---------------- projection GEMM (fp32, split-K=8; reads g_hf) --------------
__global__ void __launch_bounds__(256, 2)
proj_gemm(const float* __restrict__ Wout)
{
    __shared__ float As[2][8][132];
    __shared__ float Bs[2][8][68];

    const float* __restrict__ h = g_hf;
    int tid = threadIdx.x;
    int n0 = blockIdx.x * 64;
    int m0 = blockIdx.y * 128;
    int ks = blockIdx.z;
    int kbase = ks * 128;

    int lmA = tid >> 1, lkA = (tid & 1) * 4;
    int lmB = tid >> 2, lkB = (tid & 3) * 2;
    int ty = tid >> 4, tx = tid & 15;

    float acc[8][4];
    #pragma unroll
    for (int i = 0; i < 8; i++)
        #pragma unroll
        for (int j = 0; j < 4; j++) acc[i][j] = 0.f;

    float4 aR; float2 bR;
    int dB = n0 + lmB;

    aR = *(const float4*)&h[(m0 + lmA) * H_ + kbase + lkA];
    bR = (dB < D_) ? *(const float2*)&Wout[dB * H_ + kbase + lkB] : make_float2(0.f, 0.f);
    As[0][lkA + 0][lmA] = aR.x; As[0][lkA + 1][lmA] = aR.y;
    As[0][lkA + 2][lmA] = aR.z; As[0][lkA + 3][lmA] = aR.w;
    Bs[0][lkB + 0][lmB] = bR.x; Bs[0][lkB + 1][lmB] = bR.y;
    __syncthreads();

    const int NC = 16;
    for (int ch = 1; ch <= NC; ch++) {
        if (ch < NC) {
            int k0 = kbase + ch * 8;
            aR = *(const float4*)&h[(m0 + lmA) * H_ + k0 + lkA];
            bR = (dB < D_) ? *(const float2*)&Wout[dB * H_ + k0 + lkB] : make_float2(0.f, 0.f);
        }
        int cb = (ch - 1) & 1;
        #pragma unroll
        for (int k = 0; k < 8; k++) {
            float4 a0 = *(const float4*)&As[cb][k][ty * 8];
            float4 a1 = *(const float4*)&As[cb][k][ty * 8 + 4];
            float4 bb = *(const float4*)&Bs[cb][k][tx * 4];
            float av[8] = {a0.x, a0.y, a0.z, a0.w, a1.x, a1.y, a1.z, a1.w};
            float bv[4] = {bb.x, bb.y, bb.z, bb.w};
            #pragma unroll
            for (int i = 0; i < 8; i++)
                #pragma unroll
                for (int j = 0; j < 4; j++)
                    acc[i][j] += av[i] * bv[j];
        }
        if (ch < NC) {
            int sbuf = ch & 1;
            As[sbuf][lkA + 0][lmA] = aR.x; As[sbuf][lkA + 1][lmA] = aR.y;
            As[sbuf][lkA + 2][lmA] = aR.z; As[sbuf][lkA + 3][lmA] = aR.w;
            Bs[sbuf][lkB + 0][lmB] = bR.x; Bs[sbuf][lkB + 1][lmB] = bR.y;
        }
        __syncthreads();
    }

    #pragma unroll
    for (int i = 0; i < 8; i++)
        #pragma unroll
        for (int j = 0; j < 4; j++) {
            int col = n0 + tx * 4 + j;
            if (col < D_)
                g_proj[ks][(m0 + ty * 8 + i) * D_ + col] = acc[i][j];
        }
}

// ---------------- projection reduce: output + decoder-feedback split ---------
__global__ void proj_reduce(const float* __restrict__ b_out,
                            float* __restrict__ out, int t)
{
    int idx = blockIdx.x * blockDim.x + threadIdx.x;
    if (idx >= B_ * D_) return;
    int b = idx / D_;
    int d = idx - b * D_;
    float v = b_out[d];
    #pragma unroll
    for (int s = 0; s < 8; s++) v += g_proj[s][idx];
    out[b * (T_ * D_) + t * D_ + d] = v;
    __nv_bfloat16 hi = __float2bfloat16(v);
    g_xd_hi[b * XP + d] = hi;
    g_xd_lo[b * XP + d] = __float2bfloat16(v - __bfloat162float(hi));
}

// ---------------- host orchestration ----------------------------------------
extern "C" void kernel_launch(void* const* d_in, const int* in_sizes, int n_in,
                              void* d_out, int out_size)
{
    (void)in_sizes; (void)n_in; (void)out_size;
    const float* src   = (const float*)d_in[0];
    const float* W_ih  = (const float*)d_in[2];
    const float* W_hh  = (const float*)d_in[3];
    const float* b_ih  = (const float*)d_in[4];
    const float* b_hh  = (const float*)d_in[5];
    const float* W_out = (const float*)d_in[6];
    const float* b_out = (const float*)d_in[7];
    float* out = (float*)d_out;

    cudaFuncSetAttribute(lstm_step_mma,
                         cudaFuncAttributeMaxDynamicSharedMemorySize, SMEM_DYN);

    prep_weights<<<(G_ * KP) / 256, 256>>>(W_ih, W_hh, b_ih, b_hh);
    prep_xe<<<(S_ * B_ * XP) / 256, 256>>>(src);
    init_state<<<(B_ * H_) / 256, 256>>>();

    dim3 gg(G_ / 64, B_ / 64);    // (64, 4) = 256 CTAs
    dim3 pg(4, B_ / 128, 8);
    int cur = 0;

    // Encoder
    for (int t = 0; t < S_; t++) {
        lstm_step_mma<<<gg, 128, SMEM_DYN>>>(cur, 0, t * B_ * XP);
        cur ^= 1;
    }
    // Decoder
    for (int t = 0; t < T_; t++) {
        if (t == 0)
            lstm_step_mma<<<gg, 128, SMEM_DYN>>>(cur, 0, (S_ - 1) * B_ * XP);
        else
            lstm_step_mma<<<gg, 128, SMEM_DYN>>>(cur, 1, 0);
        cur ^= 1;
        proj_gemm<<<pg, 256>>>(W_out);
        proj_reduce<<<(B_ * D_ + 255) / 256, 256>>>(b_out, out, t);
    }
}

// round 9
// speedup vs baseline: 1.4573x; 1.4573x over previous
#include <cuda_runtime.h>
#include <cuda_bf16.h>
#include <math.h>
#include <stdint.h>

#define B_ 256
#define S_ 120
#define T_ 24
#define D_ 216
#define H_ 1024
#define G_ 4096           // 4*H
#define KP 1280           // padded K (1024 h + 216 x + 40 zero)
#define XP 256            // padded x row width
#define BK 32
#define NCH (KP / BK)     // 40
#define A_PITCH 80
#define SPLIT_BYTES 5184               // 64*80 + 64B rotation (store-bank spread)
#define STAGE_BYTES (4 * SPLIT_BYTES)  // 20736
#define NSTAGE 3
#define SMEM_DYN (NSTAGE * STAGE_BYTES)  // 62208

// ---------------- device globals (no allocations allowed) --------------------
__device__ __align__(16) __nv_bfloat16 g_Wp_hi[G_ * KP];      // permuted, split
__device__ __align__(16) __nv_bfloat16 g_Wp_lo[G_ * KP];
__device__ __align__(16) __nv_bfloat16 g_xe_hi[S_ * B_ * XP]; // encoder x splits
__device__ __align__(16) __nv_bfloat16 g_xe_lo[S_ * B_ * XP];
__device__ __align__(16) __nv_bfloat16 g_xd_hi[B_ * XP];      // decoder x splits
__device__ __align__(16) __nv_bfloat16 g_xd_lo[B_ * XP];
__device__ __align__(16) __nv_bfloat16 g_ah_hi[2][B_ * H_];   // h splits, ping-pong
__device__ __align__(16) __nv_bfloat16 g_ah_lo[2][B_ * H_];
__device__ float g_hf[B_ * H_];       // fp32 h (projection input)
__device__ float g_c[B_ * H_];        // cell state
__device__ float g_bp[G_];            // permuted combined bias
__device__ float g_proj[8][B_ * D_];  // split-K projection partials

__device__ __forceinline__ float sigf(float v) { return 1.f / (1.f + expf(-v)); }

// ---------------- PTX helpers (baseline sm_80+ only) -------------------------
__device__ __forceinline__ uint32_t smem_u32(const void* p) {
    uint32_t a;
    asm("{ .reg .u64 t; cvta.to.shared.u64 t, %1; cvt.u32.u64 %0, t; }"
        : "=r"(a) : "l"(p));
    return a;
}
#define CP_ASYNC16(dst, src) \
    asm volatile("cp.async.ca.shared.global [%0], [%1], 16;" :: "r"(dst), "l"(src))
#define CP_COMMIT() asm volatile("cp.async.commit_group;" ::: "memory")
#define CP_WAIT1()  asm volatile("cp.async.wait_group 1;" ::: "memory")
#define CP_WAIT0()  asm volatile("cp.async.wait_group 0;" ::: "memory")

#define LDSM_X4(r0, r1, r2, r3, a) \
    asm volatile("ldmatrix.sync.aligned.m8n8.x4.shared.b16 {%0,%1,%2,%3}, [%4];" \
                 : "=r"(r0), "=r"(r1), "=r"(r2), "=r"(r3) : "r"(a))

#define MMA16816(d, a, b) \
    asm volatile("mma.sync.aligned.m16n8k16.row.col.f32.bf16.bf16.f32 " \
                 "{%0,%1,%2,%3},{%4,%5,%6,%7},{%8,%9},{%0,%1,%2,%3};" \
                 : "+f"((d)[0]), "+f"((d)[1]), "+f"((d)[2]), "+f"((d)[3]) \
                 : "r"((a)[0]), "r"((a)[1]), "r"((a)[2]), "r"((a)[3]), \
                   "r"((b)[0]), "r"((b)[1]))

// ---------------- prep kernels ----------------------------------------------
// Permutation: permuted col p -> bn=p>>6, c=p&63, u=c>>2, q=c&3, unit j=bn*16+u,
// original weight row = q*H_ + j. A CTA's 64 cols = 16 units x 4 gates.
__global__ void prep_weights(const float* __restrict__ W_ih,
                             const float* __restrict__ W_hh,
                             const float* __restrict__ b_ih,
                             const float* __restrict__ b_hh)
{
    int idx = blockIdx.x * blockDim.x + threadIdx.x;  // G_*KP threads
    int p = idx / KP, k = idx - p * KP;
    int bn = p >> 6, c = p & 63, u = c >> 2, q = c & 3;
    int j = bn * 16 + u;
    int orig = q * H_ + j;
    float w = 0.f;
    if (k < H_) w = W_hh[orig * H_ + k];
    else if (k < H_ + D_) w = W_ih[orig * D_ + (k - H_)];
    __nv_bfloat16 hi = __float2bfloat16(w);
    g_Wp_hi[idx] = hi;
    g_Wp_lo[idx] = __float2bfloat16(w - __bfloat162float(hi));
    if (k == 0) g_bp[p] = b_ih[orig] + b_hh[orig];
}

__global__ void prep_xe(const float* __restrict__ src)
{
    int idx = blockIdx.x * blockDim.x + threadIdx.x;  // S_*B_*XP threads
    int t = idx >> 16;            // B_*XP = 65536
    int r = idx & 65535;
    int b = r >> 8, kk = r & 255;
    float v = (kk < D_) ? src[(b * S_ + t) * D_ + kk] : 0.f;
    __nv_bfloat16 hi = __float2bfloat16(v);
    g_xe_hi[idx] = hi;
    g_xe_lo[idx] = __float2bfloat16(v - __bfloat162float(hi));
}

__global__ void init_state()
{
    int idx = blockIdx.x * blockDim.x + threadIdx.x;
    if (idx < B_ * H_) {
        g_c[idx] = 0.f;
        g_ah_hi[0][idx] = __float2bfloat16(0.f);
        g_ah_lo[0][idx] = __float2bfloat16(0.f);
    }
    if (idx < B_ * XP) {
        g_xd_hi[idx] = __float2bfloat16(0.f);
        g_xd_lo[idx] = __float2bfloat16(0.f);
    }
}

// ---------------- fused LSTM step: HMMA split-bf16 GEMM + cell ---------------
// grid (64, 4): blockIdx.x = N tile (64 permuted cols = 16 units),
//               blockIdx.y = M tile (64 batch rows).
// 256 threads = 8 warps arranged 2(M) x 2(N) x 2(K-half): each warp computes a
// 32x32 output tile for one half of each K-chunk. Fragment sharing degree is
// (2,2) -> 48KB smem traffic/chunk (vs 64KB at 4x2) while keeping 16 warps/SM.
// Cross-warp K reduction happens once per step in the smem epilogue.
__global__ void __launch_bounds__(256, 2)
lstm_step_mma(int hbuf, int xsel, int xoff)
{
    extern __shared__ __align__(128) char smem[];
    const uint32_t sb = smem_u32(smem);
    const int tid = threadIdx.x;
    const int wid = tid >> 5;
    const int lane = tid & 31;
    const int bn = blockIdx.x;
    const int m0 = blockIdx.y << 6;
    const int n0 = bn << 6;

    const __nv_bfloat16* __restrict__ ah_hi = g_ah_hi[hbuf];
    const __nv_bfloat16* __restrict__ ah_lo = g_ah_lo[hbuf];
    const __nv_bfloat16* __restrict__ x_hi = xsel ? g_xd_hi : (g_xe_hi + xoff);
    const __nv_bfloat16* __restrict__ x_lo = xsel ? g_xd_lo : (g_xe_lo + xoff);
    const __nv_bfloat16* __restrict__ wp_hi = g_Wp_hi;
    const __nv_bfloat16* __restrict__ wp_lo = g_Wp_lo;

    // stage layout: [A_hi | A_lo | B_hi | B_lo], each SPLIT_BYTES.
    // loader: A 512 x 16B + B 512 x 16B per stage -> 4 cp.async per thread.
    auto load_stage = [&](int ch, int slot) {
        uint32_t s = sb + slot * STAGE_BYTES;
        #pragma unroll
        for (int i = 0; i < 2; i++) {
            int idx = i * 256 + tid;
            int row = idx >> 3, rem = idx & 7;
            int split = rem >> 2, c4 = rem & 3;
            const __nv_bfloat16* g;
            if (ch < 32)
                g = (split ? ah_lo : ah_hi) + (size_t)(m0 + row) * H_ + ch * BK + c4 * 8;
            else
                g = (split ? x_lo : x_hi) + (size_t)(m0 + row) * XP + (ch - 32) * BK + c4 * 8;
            CP_ASYNC16(s + split * SPLIT_BYTES + row * A_PITCH + c4 * 16, g);
        }
        #pragma unroll
        for (int i = 0; i < 2; i++) {
            int idx = i * 256 + tid;
            int row = idx >> 3, rem = idx & 7;
            int split = rem >> 2, c4 = rem & 3;
            const __nv_bfloat16* g =
                (split ? wp_lo : wp_hi) + (size_t)(n0 + row) * KP + ch * BK + c4 * 8;
            CP_ASYNC16(s + (2 + split) * SPLIT_BYTES + row * A_PITCH + c4 * 16, g);
        }
    };

    const int kh    = wid & 1;         // K-half 0/1 within each 32-chunk
    const int warpM = (wid >> 1) & 1;  // rows warpM*32
    const int warpN = wid >> 2;        // cols warpN*32

    // split accumulators: accA gets hi*hi (1-deep chain), accB both cross terms.
    float accA[2][4][4], accB[2][4][4];
    #pragma unroll
    for (int mt = 0; mt < 2; mt++)
        #pragma unroll
        for (int j = 0; j < 4; j++)
            #pragma unroll
            for (int q = 0; q < 4; q++) { accA[mt][j][q] = 0.f; accB[mt][j][q] = 0.f; }

    // ldmatrix lane-address components (constant per thread)
    const int tsel = lane >> 3;          // tile index 0..3
    const int aRow = (tsel & 1) * 8 + (lane & 7);
    const int aKof = (tsel >> 1) * 16;   // bytes
    const int bRow = (tsel >> 1) * 8 + (lane & 7);
    const int bKof = (tsel & 1) * 16;    // bytes

    load_stage(0, 0); CP_COMMIT();
    load_stage(1, 1); CP_COMMIT();

    #pragma unroll 1
    for (int ch = 0; ch < NCH; ch++) {
        CP_WAIT1();                 // stage ch resident
        __syncthreads();
        if (ch + 2 < NCH) load_stage(ch + 2, (ch + 2) % NSTAGE);
        CP_COMMIT();

        uint32_t s = sb + (ch % NSTAGE) * STAGE_BYTES;
        // this warp reads only its K-half (kh*32 bytes = 16 bf16 offset)
        uint32_t a_hi[2][4], a_lo[2][4];
        #pragma unroll
        for (int mt = 0; mt < 2; mt++) {
            uint32_t ra = s + (warpM * 32 + mt * 16 + aRow) * A_PITCH
                            + kh * 32 + aKof;
            LDSM_X4(a_hi[mt][0], a_hi[mt][1], a_hi[mt][2], a_hi[mt][3], ra);
            LDSM_X4(a_lo[mt][0], a_lo[mt][1], a_lo[mt][2], a_lo[mt][3],
                    ra + SPLIT_BYTES);
        }
        uint32_t b_hi[4][2], b_lo[4][2];
        #pragma unroll
        for (int gq = 0; gq < 2; gq++) {
            uint32_t rb = s + 2 * SPLIT_BYTES
                            + (warpN * 32 + gq * 16 + bRow) * A_PITCH
                            + kh * 32 + bKof;
            uint32_t r0, r1, r2, r3;
            LDSM_X4(r0, r1, r2, r3, rb);
            b_hi[gq * 2 + 0][0] = r0; b_hi[gq * 2 + 0][1] = r1;
            b_hi[gq * 2 + 1][0] = r2; b_hi[gq * 2 + 1][1] = r3;
            LDSM_X4(r0, r1, r2, r3, rb + SPLIT_BYTES);
            b_lo[gq * 2 + 0][0] = r0; b_lo[gq * 2 + 0][1] = r1;
            b_lo[gq * 2 + 1][0] = r2; b_lo[gq * 2 + 1][1] = r3;
        }
        #pragma unroll
        for (int mt = 0; mt < 2; mt++)
            #pragma unroll
            for (int ni = 0; ni < 4; ni++) {
                MMA16816(accA[mt][ni], a_hi[mt], b_hi[ni]);
                MMA16816(accB[mt][ni], a_hi[mt], b_lo[ni]);
                MMA16816(accB[mt][ni], a_lo[mt], b_hi[ni]);
            }
    }
    CP_WAIT0();
    __syncthreads();

    // ---- epilogue: cross-warp K reduction through smem, fused LSTM cell ----
    float* gbuf = (float*)smem;           // [64][68] f32 = 17.4KB (reuses stages)
    const int GP = 68;
    // phase 1: kh=0 warps write their sums
    if (kh == 0) {
        #pragma unroll
        for (int mt = 0; mt < 2; mt++)
            #pragma unroll
            for (int ni = 0; ni < 4; ni++) {
                int r0 = warpM * 32 + mt * 16 + (lane >> 2);
                int c0 = warpN * 32 + ni * 8 + 2 * (lane & 3);
                gbuf[r0 * GP + c0]           = accA[mt][ni][0] + accB[mt][ni][0];
                gbuf[r0 * GP + c0 + 1]       = accA[mt][ni][1] + accB[mt][ni][1];
                gbuf[(r0 + 8) * GP + c0]     = accA[mt][ni][2] + accB[mt][ni][2];
                gbuf[(r0 + 8) * GP + c0 + 1] = accA[mt][ni][3] + accB[mt][ni][3];
            }
    }
    __syncthreads();
    // phase 2: kh=1 warps add theirs (distinct elements per warp -> no races)
    if (kh == 1) {
        #pragma unroll
        for (int mt = 0; mt < 2; mt++)
            #pragma unroll
            for (int ni = 0; ni < 4; ni++) {
                int r0 = warpM * 32 + mt * 16 + (lane >> 2);
                int c0 = warpN * 32 + ni * 8 + 2 * (lane & 3);
                gbuf[r0 * GP + c0]           += accA[mt][ni][0] + accB[mt][ni][0];
                gbuf[r0 * GP + c0 + 1]       += accA[mt][ni][1] + accB[mt][ni][1];
                gbuf[(r0 + 8) * GP + c0]     += accA[mt][ni][2] + accB[mt][ni][2];
                gbuf[(r0 + 8) * GP + c0 + 1] += accA[mt][ni][3] + accB[mt][ni][3];
            }
    }
    __syncthreads();

    {
        const int u = tid & 15;           // local unit 0..15
        const int rg = tid >> 4;          // row group 0..15 (4 rows each)
        const int j = bn * 16 + u;        // global hidden unit
        const float bi = g_bp[n0 + u * 4 + 0];
        const float bf = g_bp[n0 + u * 4 + 1];
        const float bg = g_bp[n0 + u * 4 + 2];
        const float bo = g_bp[n0 + u * 4 + 3];
        __nv_bfloat16* __restrict__ oh = g_ah_hi[1 - hbuf];
        __nv_bfloat16* __restrict__ ol = g_ah_lo[1 - hbuf];
        #pragma unroll
        for (int rr = 0; rr < 4; rr++) {
            int r = rg * 4 + rr;
            const float* gr = &gbuf[r * GP + u * 4];
            float gi = gr[0] + bi;
            float gf = gr[1] + bf;
            float gg = gr[2] + bg;
            float go = gr[3] + bo;
            size_t idx = (size_t)(m0 + r) * H_ + j;
            float cn = sigf(gf) * g_c[idx] + sigf(gi) * tanhf(gg);
            g_c[idx] = cn;
            float hn = sigf(go) * tanhf(cn);
            g_hf[idx] = hn;
            __nv_bfloat16 hh = __float2bfloat16(hn);
            oh[idx] = hh;
            ol[idx] = __float2bfloat16(hn - __bfloat162float(hh));
        }
    }
}

// ---------------- projection GEMM (fp32, split-K=8; reads g_hf) --------------
__global__ void __launch_bounds__(256, 2)
proj_gemm(const float* __restrict__ Wout)
{
    __shared__ float As[2][8][132];
    __shared__ float Bs[2][8][68];

    const float* __restrict__ h = g_hf;
    int tid = threadIdx.x;
    int n0 = blockIdx.x * 64;
    int m0 = blockIdx.y * 128;
    int ks = blockIdx.z;
    int kbase = ks * 128;

    int lmA = tid >> 1, lkA = (tid & 1) * 4;
    int lmB = tid >> 2, lkB = (tid & 3) * 2;
    int ty = tid >> 4, tx = tid & 15;

    float acc[8][4];
    #pragma unroll
    for (int i = 0; i < 8; i++)
        #pragma unroll
        for (int j = 0; j < 4; j++) acc[i][j] = 0.f;

    float4 aR; float2 bR;
    int dB = n0 + lmB;

    aR = *(const float4*)&h[(m0 + lmA) * H_ + kbase + lkA];
    bR = (dB < D_) ? *(const float2*)&Wout[dB * H_ + kbase + lkB] : make_float2(0.f, 0.f);
    As[0][lkA + 0][lmA] = aR.x; As[0][lkA + 1][lmA] = aR.y;
    As[0][lkA + 2][lmA] = aR.z; As[0][lkA + 3][lmA] = aR.w;
    Bs[0][lkB + 0][lmB] = bR.x; Bs[0][lkB + 1][lmB] = bR.y;
    __syncthreads();

    const int NC = 16;
    for (int ch = 1; ch <= NC; ch++) {
        if (ch < NC) {
            int k0 = kbase + ch * 8;
            aR = *(const float4*)&h[(m0 + lmA) * H_ + k0 + lkA];
            bR = (dB < D_) ? *(const float2*)&Wout[dB * H_ + k0 + lkB] : make_float2(0.f, 0.f);
        }
        int cb = (ch - 1) & 1;
        #pragma unroll
        for (int k = 0; k < 8; k++) {
            float4 a0 = *(const float4*)&As[cb][k][ty * 8];
            float4 a1 = *(const float4*)&As[cb][k][ty * 8 + 4];
            float4 bb = *(const float4*)&Bs[cb][k][tx * 4];
            float av[8] = {a0.x, a0.y, a0.z, a0.w, a1.x, a1.y, a1.z, a1.w};
            float bv[4] = {bb.x, bb.y, bb.z, bb.w};
            #pragma unroll
            for (int i = 0; i < 8; i++)
                #pragma unroll
                for (int j = 0; j < 4; j++)
                    acc[i][j] += av[i] * bv[j];
        }
        if (ch < NC) {
            int sbuf = ch & 1;
            As[sbuf][lkA + 0][lmA] = aR.x; As[sbuf][lkA + 1][lmA] = aR.y;
            As[sbuf][lkA + 2][lmA] = aR.z; As[sbuf][lkA + 3][lmA] = aR.w;
            Bs[sbuf][lkB + 0][lmB] = bR.x; Bs[sbuf][lkB + 1][lmB] = bR.y;
        }
        __syncthreads();
    }

    #pragma unroll
    for (int i = 0; i < 8; i++)
        #pragma unroll
        for (int j = 0; j < 4; j++) {
            int col = n0 + tx * 4 + j;
            if (col < D_)
                g_proj[ks][(m0 + ty * 8 + i) * D_ + col] = acc[i][j];
        }
}

// ---------------- projection reduce: output + decoder-feedback split ---------
__global__ void proj_reduce(const float* __restrict__ b_out,
                            float* __restrict__ out, int t)
{
    int idx = blockIdx.x * blockDim.x + threadIdx.x;
    if (idx >= B_ * D_) return;
    int b = idx / D_;
    int d = idx - b * D_;
    float v = b_out[d];
    #pragma unroll
    for (int s = 0; s < 8; s++) v += g_proj[s][idx];
    out[b * (T_ * D_) + t * D_ + d] = v;
    __nv_bfloat16 hi = __float2bfloat16(v);
    g_xd_hi[b * XP + d] = hi;
    g_xd_lo[b * XP + d] = __float2bfloat16(v - __bfloat162float(hi));
}

// ---------------- host orchestration ----------------------------------------
extern "C" void kernel_launch(void* const* d_in, const int* in_sizes, int n_in,
                              void* d_out, int out_size)
{
    (void)in_sizes; (void)n_in; (void)out_size;
    const float* src   = (const float*)d_in[0];
    const float* W_ih  = (const float*)d_in[2];
    const float* W_hh  = (const float*)d_in[3];
    const float* b_ih  = (const float*)d_in[4];
    const float* b_hh  = (const float*)d_in[5];
    const float* W_out = (const float*)d_in[6];
    const float* b_out = (const float*)d_in[7];
    float* out = (float*)d_out;

    cudaFuncSetAttribute(lstm_step_mma,
                         cudaFuncAttributeMaxDynamicSharedMemorySize, SMEM_DYN);

    prep_weights<<<(G_ * KP) / 256, 256>>>(W_ih, W_hh, b_ih, b_hh);
    prep_xe<<<(S_ * B_ * XP) / 256, 256>>>(src);
    init_state<<<(B_ * H_) / 256, 256>>>();

    dim3 gg(G_ / 64, B_ / 64);    // (64, 4) = 256 CTAs, 2 per SM
    dim3 pg(4, B_ / 128, 8);
    int cur = 0;

    // Encoder
    for (int t = 0; t < S_; t++) {
        lstm_step_mma<<<gg, 256, SMEM_DYN>>>(cur, 0, t * B_ * XP);
        cur ^= 1;
    }
    // Decoder
    for (int t = 0; t < T_; t++) {
        if (t == 0)
            lstm_step_mma<<<gg, 256, SMEM_DYN>>>(cur, 0, (S_ - 1) * B_ * XP);
        else
            lstm_step_mma<<<gg, 256, SMEM_DYN>>>(cur, 1, 0);
        cur ^= 1;
        proj_gemm<<<pg, 256>>>(W_out);
        proj_reduce<<<(B_ * D_ + 255) / 256, 256>>>(b_out, out, t);
    }
}